// round 1
// baseline (speedup 1.0000x reference)
#include <cuda_runtime.h>
#include <cstdint>
#include <cfloat>

#define BROWS 8192
#define DIM   2048
#define NBLK  (BROWS/128)

// Persistent scratch (allocation-free rule: __device__ globals)
__device__ float g_H0[(size_t)BROWS * DIM];
__device__ float g_H1[(size_t)BROWS * DIM];
__device__ float g_H2[(size_t)BROWS * DIM];
__device__ int   g_route[BROWS];
__device__ float g_minmax[2];
__device__ int   g_need1[NBLK];
__device__ int   g_need2[NBLK];

// ---------------------------------------------------------------------------
// Kernel 1: exact min/max of uncertainty + zero the per-tile need flags
// ---------------------------------------------------------------------------
__global__ void minmax_kernel(const float* __restrict__ unc) {
    __shared__ float smin[256], smax[256];
    float mn = FLT_MAX, mx = -FLT_MAX;
    for (int i = threadIdx.x; i < BROWS; i += 256) {
        float v = unc[i];
        mn = fminf(mn, v);
        mx = fmaxf(mx, v);
    }
    smin[threadIdx.x] = mn;
    smax[threadIdx.x] = mx;
    __syncthreads();
    for (int s = 128; s > 0; s >>= 1) {
        if (threadIdx.x < s) {
            smin[threadIdx.x] = fminf(smin[threadIdx.x], smin[threadIdx.x + s]);
            smax[threadIdx.x] = fmaxf(smax[threadIdx.x], smax[threadIdx.x + s]);
        }
        __syncthreads();
    }
    if (threadIdx.x == 0) { g_minmax[0] = smin[0]; g_minmax[1] = smax[0]; }
    if (threadIdx.x < NBLK) { g_need1[threadIdx.x] = 0; g_need2[threadIdx.x] = 0; }
}

// ---------------------------------------------------------------------------
// Kernel 2: router MLP 1->32->16->3, argmax (softmax is monotone), flags
// ---------------------------------------------------------------------------
__global__ void route_kernel(const float* __restrict__ unc,
                             const float* __restrict__ rw1, const float* __restrict__ rb1,
                             const float* __restrict__ rw2, const float* __restrict__ rb2,
                             const float* __restrict__ rw3, const float* __restrict__ rb3,
                             float* __restrict__ out_mask) {
    __shared__ float s_w1[32], s_b1[32], s_w2[32 * 16], s_b2[16], s_w3[16 * 3], s_b3[3];
    int t = threadIdx.x;
    if (t < 32) { s_w1[t] = rw1[t]; s_b1[t] = rb1[t]; }
    for (int i = t; i < 512; i += 256) s_w2[i] = rw2[i];
    if (t < 16) s_b2[t] = rb2[t];
    if (t < 48) s_w3[t] = rw3[t];
    if (t < 3)  s_b3[t] = rb3[t];
    __syncthreads();

    int i = blockIdx.x * 256 + t;
    float mn = g_minmax[0], mx = g_minmax[1];
    float u = (unc[i] - mn) / (mx - mn + 1e-8f);

    float h1[32];
#pragma unroll
    for (int j = 0; j < 32; j++) h1[j] = fmaxf(fmaf(u, s_w1[j], s_b1[j]), 0.f);
    float h2[16];
#pragma unroll
    for (int j = 0; j < 16; j++) {
        float a = s_b2[j];
#pragma unroll
        for (int k = 0; k < 32; k++) a = fmaf(h1[k], s_w2[k * 16 + j], a);
        h2[j] = fmaxf(a, 0.f);
    }
    float l[3];
#pragma unroll
    for (int j = 0; j < 3; j++) {
        float a = s_b3[j];
#pragma unroll
        for (int k = 0; k < 16; k++) a = fmaf(h2[k], s_w3[k * 3 + j], a);
        l[j] = a;
    }
    int r = 0;
    float best = l[0];
    if (l[1] > best) { best = l[1]; r = 1; }
    if (l[2] > best) { best = l[2]; r = 2; }

    g_route[i]  = r;
    out_mask[i] = (float)r;
    if (r >= 1) atomicOr(&g_need1[i >> 7], 1);
    if (r == 2) atomicOr(&g_need2[i >> 7], 1);
}

// ---------------------------------------------------------------------------
// TF32 tensor-core GEMM + bias + tanh-GELU epilogue with routed output writes
// Tile: 128x128x32, 256 threads (8 warps, 2x4), warp tile 64x32, mma m16n8k8
// ---------------------------------------------------------------------------
__device__ __forceinline__ uint32_t f2tf32(float x) {
    uint32_t y;
    asm("cvt.rna.tf32.f32 %0, %1;" : "=r"(y) : "f"(x));
    return y;
}
__device__ __forceinline__ float gelu_f(float x) {
    float x3 = x * x * x;
    float t = tanhf(0.7978845608028654f * (x + 0.044715f * x3));
    return 0.5f * x * (1.f + t);
}

#define BM 128
#define BN 128
#define BK 32

__global__ __launch_bounds__(256, 2)
void layer_kernel(const float* __restrict__ Xin, const float* __restrict__ Wall,
                  const float* __restrict__ ball, float* __restrict__ outp,
                  int layerIdx, int abuf, int hbuf, int outLevel, int needSel) {
    int bm = blockIdx.y, bn = blockIdx.x;
    if (needSel == 1 && !g_need1[bm]) return;
    if (needSel == 2 && !g_need2[bm]) return;

    const float* A = (abuf == 0) ? Xin : (abuf == 1 ? g_H0 : (abuf == 2 ? g_H1 : g_H2));
    float* Hptr = (hbuf == 1) ? g_H0 : (hbuf == 2 ? g_H1 : (hbuf == 3 ? g_H2 : nullptr));
    const float* W    = Wall + (size_t)layerIdx * DIM * DIM;
    const float* bias = ball + layerIdx * DIM;

    __shared__ uint32_t As[BM][BK + 4];   // stride 36: conflict-free frag loads
    __shared__ uint32_t Bs[BK][BN + 8];   // stride 136: conflict-free frag loads

    int tid  = threadIdx.x;
    int warp = tid >> 5, lane = tid & 31;
    int wm = warp >> 2, wn = warp & 3;     // 2 x 4 warp grid
    int gq = lane >> 2, tr = lane & 3;

    float acc[4][4][4];
#pragma unroll
    for (int i = 0; i < 4; i++)
#pragma unroll
        for (int j = 0; j < 4; j++)
#pragma unroll
            for (int r = 0; r < 4; r++) acc[i][j][r] = 0.f;

    const float* Ab = A + (size_t)bm * BM * DIM;
    const float* Wb = W + bn * BN;

    for (int kt = 0; kt < DIM; kt += BK) {
        // A tile 128x32
        {
            int c4 = (tid & 7) * 4, r0 = tid >> 3;
#pragma unroll
            for (int it = 0; it < 4; it++) {
                int r = r0 + it * 32;
                float4 v = *(const float4*)(Ab + (size_t)r * DIM + kt + c4);
                uint4 w;
                w.x = f2tf32(v.x); w.y = f2tf32(v.y); w.z = f2tf32(v.z); w.w = f2tf32(v.w);
                *(uint4*)&As[r][c4] = w;
            }
        }
        // W tile 32x128
        {
            int c4 = (tid & 31) * 4, r0 = tid >> 5;
#pragma unroll
            for (int it = 0; it < 4; it++) {
                int r = r0 + it * 8;
                float4 v = *(const float4*)(Wb + (size_t)(kt + r) * DIM + c4);
                uint4 w;
                w.x = f2tf32(v.x); w.y = f2tf32(v.y); w.z = f2tf32(v.z); w.w = f2tf32(v.w);
                *(uint4*)&Bs[r][c4] = w;
            }
        }
        __syncthreads();

#pragma unroll
        for (int k8 = 0; k8 < BK; k8 += 8) {
            uint32_t af[4][4], bf[4][2];
#pragma unroll
            for (int i = 0; i < 4; i++) {
                int row = wm * 64 + i * 16 + gq;
                int col = k8 + tr;
                af[i][0] = As[row][col];
                af[i][1] = As[row + 8][col];
                af[i][2] = As[row][col + 4];
                af[i][3] = As[row + 8][col + 4];
            }
#pragma unroll
            for (int j = 0; j < 4; j++) {
                int coln = wn * 32 + j * 8 + gq;
                int rk = k8 + tr;
                bf[j][0] = Bs[rk][coln];
                bf[j][1] = Bs[rk + 4][coln];
            }
#pragma unroll
            for (int i = 0; i < 4; i++)
#pragma unroll
                for (int j = 0; j < 4; j++) {
                    asm volatile(
                        "mma.sync.aligned.m16n8k8.row.col.f32.tf32.tf32.f32 "
                        "{%0,%1,%2,%3}, {%4,%5,%6,%7}, {%8,%9}, {%0,%1,%2,%3};"
                        : "+f"(acc[i][j][0]), "+f"(acc[i][j][1]),
                          "+f"(acc[i][j][2]), "+f"(acc[i][j][3])
                        : "r"(af[i][0]), "r"(af[i][1]), "r"(af[i][2]), "r"(af[i][3]),
                          "r"(bf[j][0]), "r"(bf[j][1]));
                }
        }
        __syncthreads();
    }

    // Epilogue: bias + GELU; write H (next-layer input) and routed output rows
    int rbase = bm * BM + wm * 64;
    int cbase = bn * BN + wn * 32;
#pragma unroll
    for (int i = 0; i < 4; i++) {
        int row0 = rbase + i * 16 + gq;
        int row1 = row0 + 8;
        int rt0 = g_route[row0], rt1 = g_route[row1];
#pragma unroll
        for (int j = 0; j < 4; j++) {
            int col = cbase + j * 8 + 2 * tr;
            float b0 = bias[col], b1 = bias[col + 1];
            float v00 = gelu_f(acc[i][j][0] + b0);
            float v01 = gelu_f(acc[i][j][1] + b1);
            float v10 = gelu_f(acc[i][j][2] + b0);
            float v11 = gelu_f(acc[i][j][3] + b1);
            if (Hptr) {
                *(float2*)&Hptr[(size_t)row0 * DIM + col] = make_float2(v00, v01);
                *(float2*)&Hptr[(size_t)row1 * DIM + col] = make_float2(v10, v11);
            }
            if (outp) {
                if (rt0 == outLevel) *(float2*)&outp[(size_t)row0 * DIM + col] = make_float2(v00, v01);
                if (rt1 == outLevel) *(float2*)&outp[(size_t)row1 * DIM + col] = make_float2(v10, v11);
            }
        }
    }
}

// ---------------------------------------------------------------------------
extern "C" void kernel_launch(void* const* d_in, const int* in_sizes, int n_in,
                              void* d_out, int out_size) {
    const float* x   = (const float*)d_in[0];
    const float* unc = (const float*)d_in[1];
    const float* Ws  = (const float*)d_in[2];
    const float* bs  = (const float*)d_in[3];
    const float* rw1 = (const float*)d_in[4];
    const float* rb1 = (const float*)d_in[5];
    const float* rw2 = (const float*)d_in[6];
    const float* rb2 = (const float*)d_in[7];
    const float* rw3 = (const float*)d_in[8];
    const float* rb3 = (const float*)d_in[9];

    float* out  = (float*)d_out;
    float* mask = out + (size_t)BROWS * DIM;

    minmax_kernel<<<1, 256>>>(unc);
    route_kernel<<<32, 256>>>(unc, rw1, rb1, rw2, rb2, rw3, rb3, mask);

    dim3 grid(DIM / BN, BROWS / BM);  // (16, 64)
    // L0: in=x,  H=g_H0, rows with route==0 -> out ; never skipped
    layer_kernel<<<grid, 256>>>(x, Ws, bs, out, 0, 0, 1, 0, 0);
    // L1: in=H0, H=g_H1, rows with route==1 -> out ; skip tiles with no route>=1
    layer_kernel<<<grid, 256>>>(x, Ws, bs, out, 1, 1, 2, 1, 1);
    // L2: in=H1, H=g_H2 ; skip tiles with no route==2
    layer_kernel<<<grid, 256>>>(x, Ws, bs, nullptr, 2, 2, 3, -1, 2);
    // L3: in=H2, rows with route==2 -> out ; skip tiles with no route==2
    layer_kernel<<<grid, 256>>>(x, Ws, bs, out, 3, 3, 0, 2, 2);
}

// round 3
// speedup vs baseline: 1.1463x; 1.1463x over previous
#include <cuda_runtime.h>
#include <cstdint>
#include <cfloat>

#define BROWS 8192
#define DIM   2048
#define NBLK  (BROWS/128)

#define BM 128
#define BN 128
#define BK 32
#define NCH (DIM/BK)            // 64 k-iterations
// padded smem tiles (uint32 elements): As[128][36], Bs[32][136]
#define A_SM_BYTES (128*36*4)   // 18432
#define B_SM_BYTES (32*136*4)   // 17408
#define STAGE_BYTES (A_SM_BYTES + B_SM_BYTES)  // 35840
#define NSTAGE 3
#define SMEM_TOTAL (NSTAGE*STAGE_BYTES)        // 107520

// ------------------------- persistent device scratch -------------------------
__device__ __align__(16) float g_X[(size_t)BROWS * DIM];        // tf32-rounded x
__device__ __align__(16) float g_W[(size_t)4 * DIM * DIM];      // tf32-rounded W (native [l][k][n])
__device__ __align__(16) float g_H0[(size_t)BROWS * DIM];
__device__ __align__(16) float g_H1[(size_t)BROWS * DIM];
__device__ __align__(16) float g_H2[(size_t)BROWS * DIM];
__device__ int   g_route[BROWS];
__device__ float g_minmax[2];
__device__ int   g_need1[NBLK];
__device__ int   g_need2[NBLK];

// ------------------------------- helpers --------------------------------
__device__ __forceinline__ uint32_t smem_u32(const void* p) {
    uint32_t a;
    asm("{ .reg .u64 t; cvta.to.shared.u64 t, %1; cvt.u32.u64 %0, t; }" : "=r"(a) : "l"(p));
    return a;
}
__device__ __forceinline__ uint32_t f2tf32(float x) {
    uint32_t y; asm("cvt.rna.tf32.f32 %0, %1;" : "=r"(y) : "f"(x)); return y;
}
#define CP_ASYNC16(dst, src) \
    asm volatile("cp.async.cg.shared.global [%0], [%1], 16;" :: "r"(dst), "l"(src) : "memory")

__device__ __forceinline__ float gelu_f(float x) {
    float x3 = x * x * x;
    float t = tanhf(0.7978845608028654f * (x + 0.044715f * x3));
    return 0.5f * x * (1.f + t);
}

// ---------------------------------------------------------------------------
// minmax + flag reset
// ---------------------------------------------------------------------------
__global__ void minmax_kernel(const float* __restrict__ unc) {
    __shared__ float smin[256], smax[256];
    float mn = FLT_MAX, mx = -FLT_MAX;
    for (int i = threadIdx.x; i < BROWS; i += 256) {
        float v = unc[i];
        mn = fminf(mn, v); mx = fmaxf(mx, v);
    }
    smin[threadIdx.x] = mn; smax[threadIdx.x] = mx;
    __syncthreads();
    for (int s = 128; s > 0; s >>= 1) {
        if (threadIdx.x < s) {
            smin[threadIdx.x] = fminf(smin[threadIdx.x], smin[threadIdx.x + s]);
            smax[threadIdx.x] = fmaxf(smax[threadIdx.x], smax[threadIdx.x + s]);
        }
        __syncthreads();
    }
    if (threadIdx.x == 0) { g_minmax[0] = smin[0]; g_minmax[1] = smax[0]; }
    if (threadIdx.x < NBLK) { g_need1[threadIdx.x] = 0; g_need2[threadIdx.x] = 0; }
}

// ---------------------------------------------------------------------------
// router MLP (argmax == softmax argmax)
// ---------------------------------------------------------------------------
__global__ void route_kernel(const float* __restrict__ unc,
                             const float* __restrict__ rw1, const float* __restrict__ rb1,
                             const float* __restrict__ rw2, const float* __restrict__ rb2,
                             const float* __restrict__ rw3, const float* __restrict__ rb3,
                             float* __restrict__ out_mask) {
    __shared__ float s_w1[32], s_b1[32], s_w2[512], s_b2[16], s_w3[48], s_b3[3];
    int t = threadIdx.x;
    if (t < 32) { s_w1[t] = rw1[t]; s_b1[t] = rb1[t]; }
    for (int i = t; i < 512; i += 256) s_w2[i] = rw2[i];
    if (t < 16) s_b2[t] = rb2[t];
    if (t < 48) s_w3[t] = rw3[t];
    if (t < 3)  s_b3[t] = rb3[t];
    __syncthreads();

    int i = blockIdx.x * 256 + t;
    float mn = g_minmax[0], mx = g_minmax[1];
    float u = (unc[i] - mn) / (mx - mn + 1e-8f);

    float h1[32];
#pragma unroll
    for (int j = 0; j < 32; j++) h1[j] = fmaxf(fmaf(u, s_w1[j], s_b1[j]), 0.f);
    float h2[16];
#pragma unroll
    for (int j = 0; j < 16; j++) {
        float a = s_b2[j];
#pragma unroll
        for (int k = 0; k < 32; k++) a = fmaf(h1[k], s_w2[k * 16 + j], a);
        h2[j] = fmaxf(a, 0.f);
    }
    float l[3];
#pragma unroll
    for (int j = 0; j < 3; j++) {
        float a = s_b3[j];
#pragma unroll
        for (int k = 0; k < 16; k++) a = fmaf(h2[k], s_w3[k * 3 + j], a);
        l[j] = a;
    }
    int r = 0; float best = l[0];
    if (l[1] > best) { best = l[1]; r = 1; }
    if (l[2] > best) { best = l[2]; r = 2; }

    g_route[i]  = r;
    out_mask[i] = (float)r;
    if (r >= 1) atomicOr(&g_need1[i >> 7], 1);
    if (r == 2) atomicOr(&g_need2[i >> 7], 1);
}

// ---------------------------------------------------------------------------
// prep: elementwise tf32 rounding of x and W (no transpose needed)
// ---------------------------------------------------------------------------
__global__ void convx_kernel(const float* __restrict__ x) {
    size_t i = ((size_t)blockIdx.x * 256 + threadIdx.x) * 4;
    float4 v = *(const float4*)(x + i);
    v.x = __uint_as_float(f2tf32(v.x)); v.y = __uint_as_float(f2tf32(v.y));
    v.z = __uint_as_float(f2tf32(v.z)); v.w = __uint_as_float(f2tf32(v.w));
    *(float4*)(g_X + i) = v;
}
__global__ void convw_kernel(const float* __restrict__ Ws) {
    size_t i = ((size_t)blockIdx.x * 256 + threadIdx.x) * 4;
    float4 v = *(const float4*)(Ws + i);
    v.x = __uint_as_float(f2tf32(v.x)); v.y = __uint_as_float(f2tf32(v.y));
    v.z = __uint_as_float(f2tf32(v.z)); v.w = __uint_as_float(f2tf32(v.w));
    *(float4*)(g_W + i) = v;
}

// ---------------------------------------------------------------------------
// TF32 mma.sync GEMM, 3-stage cp.async pipeline.
// CTA 128x128x32, 256 threads (8 warps 2x4), warp tile 64x32, m16n8k8.
// ---------------------------------------------------------------------------
__global__ __launch_bounds__(256, 2)
void gemm_kernel(const float* __restrict__ ball, float* __restrict__ outp,
                 int layerIdx, int abuf, int hbuf, int outLevel, int needSel) {
    int bn = blockIdx.x, bm = blockIdx.y;
    if (needSel == 1 && !g_need1[bm]) return;
    if (needSel == 2 && !g_need2[bm]) return;

    extern __shared__ char smem[];
    uint32_t smem_base = smem_u32(smem);

    const float* A = (abuf == 0) ? g_X : (abuf == 1 ? g_H0 : (abuf == 2 ? g_H1 : g_H2));
    float* Hptr = (hbuf == 1) ? g_H0 : (hbuf == 2 ? g_H1 : (hbuf == 3 ? g_H2 : nullptr));
    const float* bias = ball + layerIdx * DIM;
    const char* aSrc = (const char*)(A + (size_t)bm * BM * DIM);
    const char* bSrc = (const char*)(g_W + (size_t)layerIdx * DIM * DIM + (size_t)bn * BN);

    int tid  = threadIdx.x;
    int warp = tid >> 5, lane = tid & 31;
    int wm = warp >> 2, wn = warp & 3;
    int gq = lane >> 2, tr = lane & 3;

    float acc[4][4][4];
#pragma unroll
    for (int i = 0; i < 4; i++)
#pragma unroll
        for (int j = 0; j < 4; j++)
#pragma unroll
            for (int r = 0; r < 4; r++) acc[i][j][r] = 0.f;

    // --- async load issuer: 8 x 16B cp.async per thread per stage ---
    auto issue = [&](int c) {
        int slot = c % NSTAGE;
        uint32_t ab = smem_base + slot * STAGE_BYTES;
        uint32_t bb = ab + A_SM_BYTES;
        // A tile: 128 rows x 8 granules (16B each); padded row stride 144B
        #pragma unroll
        for (int i = 0; i < 4; i++) {
            int g = tid + i * 256;
            int r = g >> 3, gc = g & 7;
            CP_ASYNC16(ab + (uint32_t)(r * 144 + gc * 16),
                       aSrc + (size_t)r * (DIM * 4) + (size_t)c * (BK * 4) + gc * 16);
        }
        // B tile: 32 rows x 32 granules; padded row stride 544B
        #pragma unroll
        for (int i = 0; i < 4; i++) {
            int g = tid + i * 256;
            int r = g >> 5, gc = g & 31;
            CP_ASYNC16(bb + (uint32_t)(r * 544 + gc * 16),
                       bSrc + (size_t)(c * BK + r) * (DIM * 4) + gc * 16);
        }
        asm volatile("cp.async.commit_group;" ::: "memory");
    };

    issue(0);
    issue(1);

    for (int c = 0; c < NCH; c++) {
        if (c < NCH - 1) asm volatile("cp.async.wait_group 1;" ::: "memory");
        else             asm volatile("cp.async.wait_group 0;" ::: "memory");
        __syncthreads();
        if (c + 2 < NCH) issue(c + 2);

        int slot = c % NSTAGE;
        const uint32_t* As = (const uint32_t*)(smem + slot * STAGE_BYTES);
        const uint32_t* Bs = (const uint32_t*)(smem + slot * STAGE_BYTES + A_SM_BYTES);

#pragma unroll
        for (int k8 = 0; k8 < BK; k8 += 8) {
            uint32_t af[4][4], bf[4][2];
#pragma unroll
            for (int i = 0; i < 4; i++) {
                int row = wm * 64 + i * 16 + gq;
                int col = k8 + tr;
                af[i][0] = As[row * 36 + col];
                af[i][1] = As[(row + 8) * 36 + col];
                af[i][2] = As[row * 36 + col + 4];
                af[i][3] = As[(row + 8) * 36 + col + 4];
            }
#pragma unroll
            for (int j = 0; j < 4; j++) {
                int coln = wn * 32 + j * 8 + gq;
                int rk = k8 + tr;
                bf[j][0] = Bs[rk * 136 + coln];
                bf[j][1] = Bs[(rk + 4) * 136 + coln];
            }
#pragma unroll
            for (int i = 0; i < 4; i++)
#pragma unroll
                for (int j = 0; j < 4; j++) {
                    asm volatile(
                        "mma.sync.aligned.m16n8k8.row.col.f32.tf32.tf32.f32 "
                        "{%0,%1,%2,%3}, {%4,%5,%6,%7}, {%8,%9}, {%0,%1,%2,%3};"
                        : "+f"(acc[i][j][0]), "+f"(acc[i][j][1]),
                          "+f"(acc[i][j][2]), "+f"(acc[i][j][3])
                        : "r"(af[i][0]), "r"(af[i][1]), "r"(af[i][2]), "r"(af[i][3]),
                          "r"(bf[j][0]), "r"(bf[j][1]));
                }
        }
        __syncthreads();
    }

    // ---- epilogue: bias + GELU; H stored tf32-rounded, routed rows -> out ----
    int rbase = bm * BM + wm * 64;
    int cbase = bn * BN + wn * 32;
#pragma unroll
    for (int i = 0; i < 4; i++) {
        int row0 = rbase + i * 16 + gq;
        int row1 = row0 + 8;
        int rt0 = g_route[row0], rt1 = g_route[row1];
#pragma unroll
        for (int j = 0; j < 4; j++) {
            int col = cbase + j * 8 + 2 * tr;
            float b0 = bias[col], b1 = bias[col + 1];
            float v00 = gelu_f(acc[i][j][0] + b0);
            float v01 = gelu_f(acc[i][j][1] + b1);
            float v10 = gelu_f(acc[i][j][2] + b0);
            float v11 = gelu_f(acc[i][j][3] + b1);
            if (Hptr) {
                float2 h0 = make_float2(__uint_as_float(f2tf32(v00)), __uint_as_float(f2tf32(v01)));
                float2 h1 = make_float2(__uint_as_float(f2tf32(v10)), __uint_as_float(f2tf32(v11)));
                *(float2*)&Hptr[(size_t)row0 * DIM + col] = h0;
                *(float2*)&Hptr[(size_t)row1 * DIM + col] = h1;
            }
            if (outp) {
                if (rt0 == outLevel) *(float2*)&outp[(size_t)row0 * DIM + col] = make_float2(v00, v01);
                if (rt1 == outLevel) *(float2*)&outp[(size_t)row1 * DIM + col] = make_float2(v10, v11);
            }
        }
    }
}

// ---------------------------------------------------------------------------
extern "C" void kernel_launch(void* const* d_in, const int* in_sizes, int n_in,
                              void* d_out, int out_size) {
    const float* x   = (const float*)d_in[0];
    const float* unc = (const float*)d_in[1];
    const float* Ws  = (const float*)d_in[2];
    const float* bs  = (const float*)d_in[3];
    const float* rw1 = (const float*)d_in[4];
    const float* rb1 = (const float*)d_in[5];
    const float* rw2 = (const float*)d_in[6];
    const float* rb2 = (const float*)d_in[7];
    const float* rw3 = (const float*)d_in[8];
    const float* rb3 = (const float*)d_in[9];

    float* out  = (float*)d_out;
    float* mask = out + (size_t)BROWS * DIM;

    cudaFuncSetAttribute(gemm_kernel, cudaFuncAttributeMaxDynamicSharedMemorySize, SMEM_TOTAL);

    minmax_kernel<<<1, 256>>>(unc);
    route_kernel<<<32, 256>>>(unc, rw1, rb1, rw2, rb2, rw3, rb3, mask);
    convx_kernel<<<(BROWS * (DIM / 4)) / 256, 256>>>(x);
    convw_kernel<<<(4 * DIM * (DIM / 4)) / 256, 256>>>(Ws);

    dim3 grid(DIM / BN, BROWS / BM);  // (16, 64)
    // L0: in=g_X, H=g_H0, rows route==0 -> out
    gemm_kernel<<<grid, 256, SMEM_TOTAL>>>(bs, out,     0, 0, 1, 0,  0);
    // L1: in=H0, H=H1, rows route==1 -> out ; skip tiles with no route>=1
    gemm_kernel<<<grid, 256, SMEM_TOTAL>>>(bs, out,     1, 1, 2, 1,  1);
    // L2: in=H1, H=H2 ; skip tiles with no route==2
    gemm_kernel<<<grid, 256, SMEM_TOTAL>>>(bs, nullptr, 2, 2, 3, -1, 2);
    // L3: in=H2, rows route==2 -> out ; skip tiles with no route==2
    gemm_kernel<<<grid, 256, SMEM_TOTAL>>>(bs, out,     3, 3, 0, 2,  2);
}